// round 7
// baseline (speedup 1.0000x reference)
#include <cuda_runtime.h>
#include <cstdint>
#include <cstddef>

// Problem constants
#define NB 16
#define NC 128
#define HW 4096          // 64*64
#define MP 1024          // pooled positions (32*32)
#define K8 16            // C/8
#define K2 64            // C/2

// ---------------- scratch (device globals; no allocation allowed) ----------------
__device__ __align__(16) float g_f[NB * K8 * MP];                 // 1 MB
__device__ __align__(16) float g_g[NB * K8 * HW];                 // 4 MB
__device__ __align__(16) float g_v[NB * K2 * MP];                 // 4 MB
__device__ __align__(16) float g_beta[(size_t)NB * MP * HW];      // 256 MB

// ---------------- helpers ----------------
__device__ __forceinline__ float wredmax(float v) {
#pragma unroll
    for (int o = 16; o > 0; o >>= 1) v = fmaxf(v, __shfl_xor_sync(0xffffffffu, v, o));
    return v;
}
__device__ __forceinline__ float wredsum(float v) {
#pragma unroll
    for (int o = 16; o > 0; o >>= 1) v += __shfl_xor_sync(0xffffffffu, v, o);
    return v;
}

// =====================================================================
// Kernel 1: fused 1x1 convs (f,g,h) + 2x2 maxpool for f,h.
// Grid: (32 row-pairs, 16 batches), 384 threads.
// Dynamic smem: xs[128][128] (64KB) + ws[96][128] (48KB, reused as cs[80][128])
// =====================================================================
__global__ void __launch_bounds__(384) conv_pool_kernel(
    const float* __restrict__ x,
    const float* __restrict__ Wf, const float* __restrict__ bf,
    const float* __restrict__ Wg, const float* __restrict__ bg,
    const float* __restrict__ Wh, const float* __restrict__ bh)
{
    extern __shared__ float sm1[];
    float* xs = sm1;            // [128][128]  pix-contiguous
    float* ws = sm1 + 16384;    // [96][128]   k rows: 0..15 f, 16..31 g, 32..95 h
    __shared__ float bs[96];

    const int tid = threadIdx.x;
    const int hp  = blockIdx.x;   // pooled row 0..31
    const int b   = blockIdx.y;

    // weights -> smem
    {
        const float4* wf4 = (const float4*)Wf;
        const float4* wg4 = (const float4*)Wg;
        const float4* wh4 = (const float4*)Wh;
        float4* ws4 = (float4*)ws;
        for (int i = tid; i < 512;  i += 384) ws4[i]        = wf4[i];
        for (int i = tid; i < 512;  i += 384) ws4[512 + i]  = wg4[i];
        for (int i = tid; i < 2048; i += 384) ws4[1024 + i] = wh4[i];
        if (tid < 96) bs[tid] = (tid < 16) ? bf[tid] : ((tid < 32) ? bg[tid - 16] : bh[tid - 32]);
    }
    // x slab: rows 2hp, 2hp+1 for all 128 channels; 128 contiguous floats per channel
    {
        float4* xs4 = (float4*)xs;
        for (int i = tid; i < 4096; i += 384) {
            int c = i >> 5, p4 = i & 31;
            xs4[i] = *((const float4*)(x + (size_t)(b * NC + c) * HW + hp * 128) + p4);
        }
    }
    __syncthreads();

    // each thread: 4 consecutive output channels (kq) x 8 pixels (pg)
    const int kq = tid >> 4;        // 0..23
    const int pg = tid & 15;        // 0..15
    const int k0 = kq * 4;
    const int px = pg * 8;

    float acc[4][8];
#pragma unroll
    for (int i = 0; i < 4; i++)
#pragma unroll
        for (int j = 0; j < 8; j++) acc[i][j] = 0.f;

    const float* wr0 = ws + (k0 + 0) * 128;
    const float* wr1 = ws + (k0 + 1) * 128;
    const float* wr2 = ws + (k0 + 2) * 128;
    const float* wr3 = ws + (k0 + 3) * 128;

#pragma unroll 2
    for (int c = 0; c < 128; c += 4) {
        float4 w0 = *(const float4*)(wr0 + c);
        float4 w1 = *(const float4*)(wr1 + c);
        float4 w2 = *(const float4*)(wr2 + c);
        float4 w3 = *(const float4*)(wr3 + c);
        float wa0[4] = {w0.x, w0.y, w0.z, w0.w};
        float wa1[4] = {w1.x, w1.y, w1.z, w1.w};
        float wa2[4] = {w2.x, w2.y, w2.z, w2.w};
        float wa3[4] = {w3.x, w3.y, w3.z, w3.w};
#pragma unroll
        for (int ci = 0; ci < 4; ci++) {
            float4 xa = *(const float4*)(xs + (c + ci) * 128 + px);
            float4 xb = *(const float4*)(xs + (c + ci) * 128 + px + 4);
            float xv[8] = {xa.x, xa.y, xa.z, xa.w, xb.x, xb.y, xb.z, xb.w};
#pragma unroll
            for (int j = 0; j < 8; j++) {
                acc[0][j] = fmaf(wa0[ci], xv[j], acc[0][j]);
                acc[1][j] = fmaf(wa1[ci], xv[j], acc[1][j]);
                acc[2][j] = fmaf(wa2[ci], xv[j], acc[2][j]);
                acc[3][j] = fmaf(wa3[ci], xv[j], acc[3][j]);
            }
        }
    }
    __syncthreads();   // done with xs & ws reads; ws region reused as cs below

    const int r    = pg >> 3;         // row within pair
    const int colb = (pg & 7) * 8;    // column base (0..56)

    if (kq >= 4 && kq < 8) {
        // g channels: full resolution, write directly
#pragma unroll
        for (int i = 0; i < 4; i++) {
            const int k = k0 + i;                 // 16..31
            const float bias = bs[k];
            float* gp = g_g + (size_t)(b * K8 + (k - 16)) * HW + (2 * hp + r) * 64 + colb;
            *(float4*)gp       = make_float4(acc[i][0] + bias, acc[i][1] + bias,
                                             acc[i][2] + bias, acc[i][3] + bias);
            *(float4*)(gp + 4) = make_float4(acc[i][4] + bias, acc[i][5] + bias,
                                             acc[i][6] + bias, acc[i][7] + bias);
        }
    } else {
        // f (k<16) and h (k>=32) channels: stage in smem for pooling
        float* cs = ws;   // [80][128]: 0..15 f, 16..79 h
#pragma unroll
        for (int i = 0; i < 4; i++) {
            const int k = k0 + i;
            const int kfh = (k < 16) ? k : (k - 16);
            const float bias = bs[k];
            float* dst = cs + kfh * 128 + px;
            *(float4*)dst       = make_float4(acc[i][0] + bias, acc[i][1] + bias,
                                              acc[i][2] + bias, acc[i][3] + bias);
            *(float4*)(dst + 4) = make_float4(acc[i][4] + bias, acc[i][5] + bias,
                                              acc[i][6] + bias, acc[i][7] + bias);
        }
    }
    __syncthreads();

    // 2x2 maxpool and writeout: 80 channels x 32 pooled cols
    for (int idx = tid; idx < 2560; idx += 384) {
        int k = idx >> 5, wc = idx & 31;
        const float* csr = ws + k * 128;
        float mv = fmaxf(fmaxf(csr[2 * wc], csr[2 * wc + 1]),
                         fmaxf(csr[64 + 2 * wc], csr[64 + 2 * wc + 1]));
        int m = hp * 32 + wc;
        if (k < 16) g_f[(size_t)(b * K8 + k) * MP + m]        = mv;
        else        g_v[(size_t)(b * K2 + (k - 16)) * MP + m] = mv;
    }
}

// =====================================================================
// Kernel 2: s = f^T g (K=16) fused with row softmax -> beta.  s never hits HBM.
// Grid: (256 m-groups of 4, 16 batches), 512 threads. Each thread: 4 rows x 8 cols.
// =====================================================================
__global__ void __launch_bounds__(512) s_softmax_kernel()
{
    const int b   = blockIdx.y;
    const int m0  = blockIdx.x * 4;
    const int tid = threadIdx.x;

    __shared__ float fs[16][4];
    __shared__ float red[4][16];

    if (tid < 64)
        fs[tid >> 2][tid & 3] = g_f[(size_t)(b * K8 + (tid >> 2)) * MP + m0 + (tid & 3)];
    __syncthreads();

    const float* gb = g_g + (size_t)b * K8 * HW;
    const int n0 = tid * 4;   // cols [n0,n0+3] and [2048+n0, 2048+n0+3]

    float acc[4][8];
#pragma unroll
    for (int mi = 0; mi < 4; mi++)
#pragma unroll
        for (int j = 0; j < 8; j++) acc[mi][j] = 0.f;

#pragma unroll
    for (int k = 0; k < 16; k++) {
        const float* gk = gb + (size_t)k * HW;
        float4 ga = *(const float4*)(gk + n0);
        float4 gc = *(const float4*)(gk + 2048 + n0);
        float gv[8] = {ga.x, ga.y, ga.z, ga.w, gc.x, gc.y, gc.z, gc.w};
#pragma unroll
        for (int mi = 0; mi < 4; mi++) {
            const float fv = fs[k][mi];
#pragma unroll
            for (int j = 0; j < 8; j++) acc[mi][j] = fmaf(fv, gv[j], acc[mi][j]);
        }
    }

    const int lane = tid & 31, wid = tid >> 5;

    // --- row max ---
    float rmx[4];
#pragma unroll
    for (int mi = 0; mi < 4; mi++) {
        float v = acc[mi][0];
#pragma unroll
        for (int j = 1; j < 8; j++) v = fmaxf(v, acc[mi][j]);
        rmx[mi] = wredmax(v);
    }
    if (lane == 0) {
#pragma unroll
        for (int mi = 0; mi < 4; mi++) red[mi][wid] = rmx[mi];
    }
    __syncthreads();
    float mxf[4];
#pragma unroll
    for (int mi = 0; mi < 4; mi++) {
        float v = red[mi][0];
#pragma unroll
        for (int w2 = 1; w2 < 16; w2++) v = fmaxf(v, red[mi][w2]);
        mxf[mi] = v;
    }
    __syncthreads();   // before reusing red[]

    // --- exp + row sum ---
    float sms[4];
#pragma unroll
    for (int mi = 0; mi < 4; mi++) {
        float s = 0.f;
#pragma unroll
        for (int j = 0; j < 8; j++) {
            acc[mi][j] = __expf(acc[mi][j] - mxf[mi]);
            s += acc[mi][j];
        }
        sms[mi] = wredsum(s);
    }
    if (lane == 0) {
#pragma unroll
        for (int mi = 0; mi < 4; mi++) red[mi][wid] = sms[mi];
    }
    __syncthreads();

#pragma unroll
    for (int mi = 0; mi < 4; mi++) {
        float s = 0.f;
#pragma unroll
        for (int w2 = 0; w2 < 16; w2++) s += red[mi][w2];
        const float inv = 1.0f / s;
        float* bp = g_beta + (size_t)(b * MP + m0 + mi) * HW + n0;
        *(float4*)bp          = make_float4(acc[mi][0] * inv, acc[mi][1] * inv,
                                            acc[mi][2] * inv, acc[mi][3] * inv);
        *(float4*)(bp + 2048) = make_float4(acc[mi][4] * inv, acc[mi][5] * inv,
                                            acc[mi][6] * inv, acc[mi][7] * inv);
    }
}

// =====================================================================
// Kernel 3: o = v @ beta  (64x4096 per batch, K=1024), fused with
// out = gamma*(Wo @ o + bo) + x.
// Grid: (32 column blocks of 128, 16 batches), 256 threads (tx 0..15, ty 0..15).
// Dyn smem: main loop As[32][68] + Bs[32][128]; epilogue Os[64][132] + WoT[64][128].
// =====================================================================
__global__ void __launch_bounds__(256) attn_out_kernel(
    const float* __restrict__ x, const float* __restrict__ Wo,
    const float* __restrict__ bo, const float* __restrict__ gammap,
    float* __restrict__ out)
{
    extern __shared__ float sm3[];
    float* As = sm3;           // [32][68]   (mi, k) with pad
    float* Bs = sm3 + 2176;    // [32][128]  (mi, n)

    const int b   = blockIdx.y;
    const int nb  = blockIdx.x * 128;
    const int tid = threadIdx.x;
    const int tx  = tid & 15, ty = tid >> 4;
    const int miL = tid & 31, kg = tid >> 5;

    const float* vB    = g_v    + (size_t)b * K2 * MP;
    const float* betaB = g_beta + (size_t)b * MP * HW + nb;

    float acc[4][8];
#pragma unroll
    for (int i = 0; i < 4; i++)
#pragma unroll
        for (int j = 0; j < 8; j++) acc[i][j] = 0.f;

    float  rA[8];
    float4 rB[4];

    // prefetch chunk 0
#pragma unroll
    for (int ii = 0; ii < 8; ii++) rA[ii] = vB[(size_t)(kg + ii * 8) * MP + miL];
#pragma unroll
    for (int it = 0; it < 4; it++) {
        int lin = it * 1024 + tid * 4;
        rB[it] = *(const float4*)(betaB + (size_t)(lin >> 7) * HW + (lin & 127));
    }
#pragma unroll
    for (int ii = 0; ii < 8; ii++) As[miL * 68 + kg + ii * 8] = rA[ii];
#pragma unroll
    for (int it = 0; it < 4; it++) *(float4*)(Bs + it * 1024 + tid * 4) = rB[it];
    __syncthreads();

    for (int c = 0; c < 32; c++) {
        const int mcn = (c + 1) * 32;
        if (c < 31) {
#pragma unroll
            for (int ii = 0; ii < 8; ii++)
                rA[ii] = vB[(size_t)(kg + ii * 8) * MP + mcn + miL];
#pragma unroll
            for (int it = 0; it < 4; it++) {
                int lin = it * 1024 + tid * 4;
                rB[it] = *(const float4*)(betaB + (size_t)(mcn + (lin >> 7)) * HW + (lin & 127));
            }
        }
#pragma unroll
        for (int mi = 0; mi < 32; mi++) {
            float4 a  = *(const float4*)(As + mi * 68 + ty * 4);
            float4 b0 = *(const float4*)(Bs + mi * 128 + tx * 8);
            float4 b1 = *(const float4*)(Bs + mi * 128 + tx * 8 + 4);
            float av[4] = {a.x, a.y, a.z, a.w};
            float bv[8] = {b0.x, b0.y, b0.z, b0.w, b1.x, b1.y, b1.z, b1.w};
#pragma unroll
            for (int i = 0; i < 4; i++)
#pragma unroll
                for (int j = 0; j < 8; j++)
                    acc[i][j] = fmaf(av[i], bv[j], acc[i][j]);
        }
        __syncthreads();
        if (c < 31) {
#pragma unroll
            for (int ii = 0; ii < 8; ii++) As[miL * 68 + kg + ii * 8] = rA[ii];
#pragma unroll
            for (int it = 0; it < 4; it++) *(float4*)(Bs + it * 1024 + tid * 4) = rB[it];
            __syncthreads();
        }
    }

    // ---------------- epilogue: out = gamma*(Wo @ o + bo) + x ----------------
    float* Os  = sm3;          // [64][132]
    float* WoT = sm3 + 8448;   // [64][128]  WoT[k][c] = Wo[c][k]

#pragma unroll
    for (int i2 = 0; i2 < 4; i2++) {
        int k = ty * 4 + i2;
        *(float4*)(Os + k * 132 + tx * 8)     = make_float4(acc[i2][0], acc[i2][1],
                                                            acc[i2][2], acc[i2][3]);
        *(float4*)(Os + k * 132 + tx * 8 + 4) = make_float4(acc[i2][4], acc[i2][5],
                                                            acc[i2][6], acc[i2][7]);
    }
    for (int i = tid; i < 8192; i += 256) {
        int k = i >> 7, cc = i & 127;
        WoT[i] = Wo[cc * 64 + k];
    }
    __syncthreads();

    const float gma = *gammap;
    float acc2[8][8];
#pragma unroll
    for (int i = 0; i < 8; i++)
#pragma unroll
        for (int j = 0; j < 8; j++) acc2[i][j] = 0.f;

#pragma unroll 4
    for (int k = 0; k < 64; k++) {
        float4 w0 = *(const float4*)(WoT + k * 128 + ty * 8);
        float4 w1 = *(const float4*)(WoT + k * 128 + ty * 8 + 4);
        float4 o0 = *(const float4*)(Os + k * 132 + tx * 8);
        float4 o1 = *(const float4*)(Os + k * 132 + tx * 8 + 4);
        float wv[8] = {w0.x, w0.y, w0.z, w0.w, w1.x, w1.y, w1.z, w1.w};
        float ov[8] = {o0.x, o0.y, o0.z, o0.w, o1.x, o1.y, o1.z, o1.w};
#pragma unroll
        for (int i = 0; i < 8; i++)
#pragma unroll
            for (int j = 0; j < 8; j++)
                acc2[i][j] = fmaf(wv[i], ov[j], acc2[i][j]);
    }

#pragma unroll
    for (int rr = 0; rr < 8; rr++) {
        const int cc = ty * 8 + rr;
        const float bias = bo[cc];
        const size_t off = (size_t)(b * NC + cc) * HW + nb + tx * 8;
        float4 x0 = *(const float4*)(x + off);
        float4 x1 = *(const float4*)(x + off + 4);
        float4 r0, r1;
        r0.x = fmaf(gma, acc2[rr][0] + bias, x0.x);
        r0.y = fmaf(gma, acc2[rr][1] + bias, x0.y);
        r0.z = fmaf(gma, acc2[rr][2] + bias, x0.z);
        r0.w = fmaf(gma, acc2[rr][3] + bias, x0.w);
        r1.x = fmaf(gma, acc2[rr][4] + bias, x1.x);
        r1.y = fmaf(gma, acc2[rr][5] + bias, x1.y);
        r1.z = fmaf(gma, acc2[rr][6] + bias, x1.z);
        r1.w = fmaf(gma, acc2[rr][7] + bias, x1.w);
        *(float4*)(out + off)     = r0;
        *(float4*)(out + off + 4) = r1;
    }
}

// =====================================================================
extern "C" void kernel_launch(void* const* d_in, const int* in_sizes, int n_in,
                              void* d_out, int out_size)
{
    (void)in_sizes; (void)n_in; (void)out_size;
    const float* x     = (const float*)d_in[0];
    const float* Wf    = (const float*)d_in[1];
    const float* bf    = (const float*)d_in[2];
    const float* Wg    = (const float*)d_in[3];
    const float* bg    = (const float*)d_in[4];
    const float* Wh    = (const float*)d_in[5];
    const float* bh    = (const float*)d_in[6];
    const float* Wo    = (const float*)d_in[7];
    const float* bo    = (const float*)d_in[8];
    const float* gamma = (const float*)d_in[9];
    float* out = (float*)d_out;

    // opt-in large dynamic smem (idempotent; safe under graph capture)
    cudaFuncSetAttribute(conv_pool_kernel,
                         cudaFuncAttributeMaxDynamicSharedMemorySize, 114688);
    cudaFuncSetAttribute(attn_out_kernel,
                         cudaFuncAttributeMaxDynamicSharedMemorySize, 66560);

    conv_pool_kernel<<<dim3(32, NB), 384, 114688>>>(x, Wf, bf, Wg, bg, Wh, bh);
    s_softmax_kernel<<<dim3(256, NB), 512>>>();
    attn_out_kernel<<<dim3(32, NB), 256, 66560>>>(x, Wo, bo, gamma, out);
}

// round 8
// speedup vs baseline: 1.0526x; 1.0526x over previous
#include <cuda_runtime.h>
#include <cstdint>
#include <cstddef>

// Problem constants
#define NB 16
#define NC 128
#define HW 4096          // 64*64
#define MP 1024          // pooled positions (32*32)
#define K8 16            // C/8
#define K2 64            // C/2

// ---------------- scratch (device globals; no allocation allowed) ----------------
__device__ __align__(16) float g_f[NB * K8 * MP];                 // 1 MB
__device__ __align__(16) float g_g[NB * K8 * HW];                 // 4 MB
__device__ __align__(16) float g_v[NB * K2 * MP];                 // 4 MB
__device__ __align__(16) float g_beta[(size_t)NB * MP * HW];      // 256 MB

// ---------------- helpers ----------------
__device__ __forceinline__ float wredmax(float v) {
#pragma unroll
    for (int o = 16; o > 0; o >>= 1) v = fmaxf(v, __shfl_xor_sync(0xffffffffu, v, o));
    return v;
}
__device__ __forceinline__ float wredsum(float v) {
#pragma unroll
    for (int o = 16; o > 0; o >>= 1) v += __shfl_xor_sync(0xffffffffu, v, o);
    return v;
}

// =====================================================================
// Kernel 1: fused 1x1 convs (f,g,h) + 2x2 maxpool for f,h.
// Grid: (32 row-pairs, 16 batches), 384 threads.
// Dynamic smem: xs[128][128] (64KB) + ws[96][128] (48KB, reused as cs[80][128])
// =====================================================================
__global__ void __launch_bounds__(384) conv_pool_kernel(
    const float* __restrict__ x,
    const float* __restrict__ Wf, const float* __restrict__ bf,
    const float* __restrict__ Wg, const float* __restrict__ bg,
    const float* __restrict__ Wh, const float* __restrict__ bh)
{
    extern __shared__ float sm1[];
    float* xs = sm1;            // [128][128]  pix-contiguous
    float* ws = sm1 + 16384;    // [96][128]   k rows: 0..15 f, 16..31 g, 32..95 h
    __shared__ float bs[96];

    const int tid = threadIdx.x;
    const int hp  = blockIdx.x;   // pooled row 0..31
    const int b   = blockIdx.y;

    // weights -> smem
    {
        const float4* wf4 = (const float4*)Wf;
        const float4* wg4 = (const float4*)Wg;
        const float4* wh4 = (const float4*)Wh;
        float4* ws4 = (float4*)ws;
        for (int i = tid; i < 512;  i += 384) ws4[i]        = wf4[i];
        for (int i = tid; i < 512;  i += 384) ws4[512 + i]  = wg4[i];
        for (int i = tid; i < 2048; i += 384) ws4[1024 + i] = wh4[i];
        if (tid < 96) bs[tid] = (tid < 16) ? bf[tid] : ((tid < 32) ? bg[tid - 16] : bh[tid - 32]);
    }
    // x slab: rows 2hp, 2hp+1 for all 128 channels; 128 contiguous floats per channel
    {
        float4* xs4 = (float4*)xs;
        for (int i = tid; i < 4096; i += 384) {
            int c = i >> 5, p4 = i & 31;
            xs4[i] = *((const float4*)(x + (size_t)(b * NC + c) * HW + hp * 128) + p4);
        }
    }
    __syncthreads();

    // each thread: 4 consecutive output channels (kq) x 8 pixels (pg)
    const int kq = tid >> 4;        // 0..23
    const int pg = tid & 15;        // 0..15
    const int k0 = kq * 4;
    const int px = pg * 8;

    float acc[4][8];
#pragma unroll
    for (int i = 0; i < 4; i++)
#pragma unroll
        for (int j = 0; j < 8; j++) acc[i][j] = 0.f;

    const float* wr0 = ws + (k0 + 0) * 128;
    const float* wr1 = ws + (k0 + 1) * 128;
    const float* wr2 = ws + (k0 + 2) * 128;
    const float* wr3 = ws + (k0 + 3) * 128;

#pragma unroll 2
    for (int c = 0; c < 128; c += 4) {
        float4 w0 = *(const float4*)(wr0 + c);
        float4 w1 = *(const float4*)(wr1 + c);
        float4 w2 = *(const float4*)(wr2 + c);
        float4 w3 = *(const float4*)(wr3 + c);
        float wa0[4] = {w0.x, w0.y, w0.z, w0.w};
        float wa1[4] = {w1.x, w1.y, w1.z, w1.w};
        float wa2[4] = {w2.x, w2.y, w2.z, w2.w};
        float wa3[4] = {w3.x, w3.y, w3.z, w3.w};
#pragma unroll
        for (int ci = 0; ci < 4; ci++) {
            float4 xa = *(const float4*)(xs + (c + ci) * 128 + px);
            float4 xb = *(const float4*)(xs + (c + ci) * 128 + px + 4);
            float xv[8] = {xa.x, xa.y, xa.z, xa.w, xb.x, xb.y, xb.z, xb.w};
#pragma unroll
            for (int j = 0; j < 8; j++) {
                acc[0][j] = fmaf(wa0[ci], xv[j], acc[0][j]);
                acc[1][j] = fmaf(wa1[ci], xv[j], acc[1][j]);
                acc[2][j] = fmaf(wa2[ci], xv[j], acc[2][j]);
                acc[3][j] = fmaf(wa3[ci], xv[j], acc[3][j]);
            }
        }
    }
    __syncthreads();   // done with xs & ws reads; ws region reused as cs below

    const int r    = pg >> 3;         // row within pair
    const int colb = (pg & 7) * 8;    // column base (0..56)

    if (kq >= 4 && kq < 8) {
        // g channels: full resolution, write directly
#pragma unroll
        for (int i = 0; i < 4; i++) {
            const int k = k0 + i;                 // 16..31
            const float bias = bs[k];
            float* gp = g_g + (size_t)(b * K8 + (k - 16)) * HW + (2 * hp + r) * 64 + colb;
            *(float4*)gp       = make_float4(acc[i][0] + bias, acc[i][1] + bias,
                                             acc[i][2] + bias, acc[i][3] + bias);
            *(float4*)(gp + 4) = make_float4(acc[i][4] + bias, acc[i][5] + bias,
                                             acc[i][6] + bias, acc[i][7] + bias);
        }
    } else {
        // f (k<16) and h (k>=32) channels: stage in smem for pooling
        float* cs = ws;   // [80][128]: 0..15 f, 16..79 h
#pragma unroll
        for (int i = 0; i < 4; i++) {
            const int k = k0 + i;
            const int kfh = (k < 16) ? k : (k - 16);
            const float bias = bs[k];
            float* dst = cs + kfh * 128 + px;
            *(float4*)dst       = make_float4(acc[i][0] + bias, acc[i][1] + bias,
                                              acc[i][2] + bias, acc[i][3] + bias);
            *(float4*)(dst + 4) = make_float4(acc[i][4] + bias, acc[i][5] + bias,
                                              acc[i][6] + bias, acc[i][7] + bias);
        }
    }
    __syncthreads();

    // 2x2 maxpool and writeout: 80 channels x 32 pooled cols
    for (int idx = tid; idx < 2560; idx += 384) {
        int k = idx >> 5, wc = idx & 31;
        const float* csr = ws + k * 128;
        float mv = fmaxf(fmaxf(csr[2 * wc], csr[2 * wc + 1]),
                         fmaxf(csr[64 + 2 * wc], csr[64 + 2 * wc + 1]));
        int m = hp * 32 + wc;
        if (k < 16) g_f[(size_t)(b * K8 + k) * MP + m]        = mv;
        else        g_v[(size_t)(b * K2 + (k - 16)) * MP + m] = mv;
    }
}

// =====================================================================
// Kernel 2: s = f^T g (K=16) fused with row softmax -> beta.  s never hits HBM.
// Grid: (256 m-groups of 4, 16 batches), 512 threads. Each thread: 4 rows x 8 cols.
// =====================================================================
__global__ void __launch_bounds__(512) s_softmax_kernel()
{
    const int b   = blockIdx.y;
    const int m0  = blockIdx.x * 4;
    const int tid = threadIdx.x;

    __shared__ float fs[16][4];
    __shared__ float red[4][16];

    if (tid < 64)
        fs[tid >> 2][tid & 3] = g_f[(size_t)(b * K8 + (tid >> 2)) * MP + m0 + (tid & 3)];
    __syncthreads();

    const float* gb = g_g + (size_t)b * K8 * HW;
    const int n0 = tid * 4;   // cols [n0,n0+3] and [2048+n0, 2048+n0+3]

    float acc[4][8];
#pragma unroll
    for (int mi = 0; mi < 4; mi++)
#pragma unroll
        for (int j = 0; j < 8; j++) acc[mi][j] = 0.f;

#pragma unroll
    for (int k = 0; k < 16; k++) {
        const float* gk = gb + (size_t)k * HW;
        float4 ga = *(const float4*)(gk + n0);
        float4 gc = *(const float4*)(gk + 2048 + n0);
        float gv[8] = {ga.x, ga.y, ga.z, ga.w, gc.x, gc.y, gc.z, gc.w};
#pragma unroll
        for (int mi = 0; mi < 4; mi++) {
            const float fv = fs[k][mi];
#pragma unroll
            for (int j = 0; j < 8; j++) acc[mi][j] = fmaf(fv, gv[j], acc[mi][j]);
        }
    }

    const int lane = tid & 31, wid = tid >> 5;

    // --- row max ---
    float rmx[4];
#pragma unroll
    for (int mi = 0; mi < 4; mi++) {
        float v = acc[mi][0];
#pragma unroll
        for (int j = 1; j < 8; j++) v = fmaxf(v, acc[mi][j]);
        rmx[mi] = wredmax(v);
    }
    if (lane == 0) {
#pragma unroll
        for (int mi = 0; mi < 4; mi++) red[mi][wid] = rmx[mi];
    }
    __syncthreads();
    float mxf[4];
#pragma unroll
    for (int mi = 0; mi < 4; mi++) {
        float v = red[mi][0];
#pragma unroll
        for (int w2 = 1; w2 < 16; w2++) v = fmaxf(v, red[mi][w2]);
        mxf[mi] = v;
    }
    __syncthreads();   // before reusing red[]

    // --- exp + row sum ---
    float sms[4];
#pragma unroll
    for (int mi = 0; mi < 4; mi++) {
        float s = 0.f;
#pragma unroll
        for (int j = 0; j < 8; j++) {
            acc[mi][j] = __expf(acc[mi][j] - mxf[mi]);
            s += acc[mi][j];
        }
        sms[mi] = wredsum(s);
    }
    if (lane == 0) {
#pragma unroll
        for (int mi = 0; mi < 4; mi++) red[mi][wid] = sms[mi];
    }
    __syncthreads();

#pragma unroll
    for (int mi = 0; mi < 4; mi++) {
        float s = 0.f;
#pragma unroll
        for (int w2 = 0; w2 < 16; w2++) s += red[mi][w2];
        const float inv = 1.0f / s;
        float* bp = g_beta + (size_t)(b * MP + m0 + mi) * HW + n0;
        *(float4*)bp          = make_float4(acc[mi][0] * inv, acc[mi][1] * inv,
                                            acc[mi][2] * inv, acc[mi][3] * inv);
        *(float4*)(bp + 2048) = make_float4(acc[mi][4] * inv, acc[mi][5] * inv,
                                            acc[mi][6] * inv, acc[mi][7] * inv);
    }
}

// =====================================================================
// Kernel 3: o = v @ beta  (64x4096 per batch, K=1024), fused with
// out = gamma*(Wo @ o + bo) + x.
// Grid: (32 column blocks of 128, 16 batches), 256 threads (tx 0..15, ty 0..15).
// Dyn smem: main loop As[32][68] + Bs[32][128]; epilogue Os[64][132] + WoT[64][128].
// =====================================================================
__global__ void __launch_bounds__(256) attn_out_kernel(
    const float* __restrict__ x, const float* __restrict__ Wo,
    const float* __restrict__ bo, const float* __restrict__ gammap,
    float* __restrict__ out)
{
    extern __shared__ float sm3[];
    float* As = sm3;           // [32][68]   (mi, k) with pad
    float* Bs = sm3 + 2176;    // [32][128]  (mi, n)

    const int b   = blockIdx.y;
    const int nb  = blockIdx.x * 128;
    const int tid = threadIdx.x;
    const int tx  = tid & 15, ty = tid >> 4;
    const int miL = tid & 31, kg = tid >> 5;

    const float* vB    = g_v    + (size_t)b * K2 * MP;
    const float* betaB = g_beta + (size_t)b * MP * HW + nb;

    float acc[4][8];
#pragma unroll
    for (int i = 0; i < 4; i++)
#pragma unroll
        for (int j = 0; j < 8; j++) acc[i][j] = 0.f;

    float  rA[8];
    float4 rB[4];

    // prefetch chunk 0
#pragma unroll
    for (int ii = 0; ii < 8; ii++) rA[ii] = vB[(size_t)(kg + ii * 8) * MP + miL];
#pragma unroll
    for (int it = 0; it < 4; it++) {
        int lin = it * 1024 + tid * 4;
        rB[it] = *(const float4*)(betaB + (size_t)(lin >> 7) * HW + (lin & 127));
    }
#pragma unroll
    for (int ii = 0; ii < 8; ii++) As[miL * 68 + kg + ii * 8] = rA[ii];
#pragma unroll
    for (int it = 0; it < 4; it++) *(float4*)(Bs + it * 1024 + tid * 4) = rB[it];
    __syncthreads();

    for (int c = 0; c < 32; c++) {
        const int mcn = (c + 1) * 32;
        if (c < 31) {
#pragma unroll
            for (int ii = 0; ii < 8; ii++)
                rA[ii] = vB[(size_t)(kg + ii * 8) * MP + mcn + miL];
#pragma unroll
            for (int it = 0; it < 4; it++) {
                int lin = it * 1024 + tid * 4;
                rB[it] = *(const float4*)(betaB + (size_t)(mcn + (lin >> 7)) * HW + (lin & 127));
            }
        }
#pragma unroll
        for (int mi = 0; mi < 32; mi++) {
            float4 a  = *(const float4*)(As + mi * 68 + ty * 4);
            float4 b0 = *(const float4*)(Bs + mi * 128 + tx * 8);
            float4 b1 = *(const float4*)(Bs + mi * 128 + tx * 8 + 4);
            float av[4] = {a.x, a.y, a.z, a.w};
            float bv[8] = {b0.x, b0.y, b0.z, b0.w, b1.x, b1.y, b1.z, b1.w};
#pragma unroll
            for (int i = 0; i < 4; i++)
#pragma unroll
                for (int j = 0; j < 8; j++)
                    acc[i][j] = fmaf(av[i], bv[j], acc[i][j]);
        }
        __syncthreads();
        if (c < 31) {
#pragma unroll
            for (int ii = 0; ii < 8; ii++) As[miL * 68 + kg + ii * 8] = rA[ii];
#pragma unroll
            for (int it = 0; it < 4; it++) *(float4*)(Bs + it * 1024 + tid * 4) = rB[it];
            __syncthreads();
        }
    }

    // ---------------- epilogue: out = gamma*(Wo @ o + bo) + x ----------------
    float* Os  = sm3;          // [64][132]
    float* WoT = sm3 + 8448;   // [64][128]  WoT[k][c] = Wo[c][k]

#pragma unroll
    for (int i2 = 0; i2 < 4; i2++) {
        int k = ty * 4 + i2;
        *(float4*)(Os + k * 132 + tx * 8)     = make_float4(acc[i2][0], acc[i2][1],
                                                            acc[i2][2], acc[i2][3]);
        *(float4*)(Os + k * 132 + tx * 8 + 4) = make_float4(acc[i2][4], acc[i2][5],
                                                            acc[i2][6], acc[i2][7]);
    }
    for (int i = tid; i < 8192; i += 256) {
        int k = i >> 7, cc = i & 127;
        WoT[i] = Wo[cc * 64 + k];
    }
    __syncthreads();

    const float gma = *gammap;
    float acc2[8][8];
#pragma unroll
    for (int i = 0; i < 8; i++)
#pragma unroll
        for (int j = 0; j < 8; j++) acc2[i][j] = 0.f;

#pragma unroll 4
    for (int k = 0; k < 64; k++) {
        float4 w0 = *(const float4*)(WoT + k * 128 + ty * 8);
        float4 w1 = *(const float4*)(WoT + k * 128 + ty * 8 + 4);
        float4 o0 = *(const float4*)(Os + k * 132 + tx * 8);
        float4 o1 = *(const float4*)(Os + k * 132 + tx * 8 + 4);
        float wv[8] = {w0.x, w0.y, w0.z, w0.w, w1.x, w1.y, w1.z, w1.w};
        float ov[8] = {o0.x, o0.y, o0.z, o0.w, o1.x, o1.y, o1.z, o1.w};
#pragma unroll
        for (int i = 0; i < 8; i++)
#pragma unroll
            for (int j = 0; j < 8; j++)
                acc2[i][j] = fmaf(wv[i], ov[j], acc2[i][j]);
    }

#pragma unroll
    for (int rr = 0; rr < 8; rr++) {
        const int cc = ty * 8 + rr;
        const float bias = bo[cc];
        const size_t off = (size_t)(b * NC + cc) * HW + nb + tx * 8;
        float4 x0 = *(const float4*)(x + off);
        float4 x1 = *(const float4*)(x + off + 4);
        float4 r0, r1;
        r0.x = fmaf(gma, acc2[rr][0] + bias, x0.x);
        r0.y = fmaf(gma, acc2[rr][1] + bias, x0.y);
        r0.z = fmaf(gma, acc2[rr][2] + bias, x0.z);
        r0.w = fmaf(gma, acc2[rr][3] + bias, x0.w);
        r1.x = fmaf(gma, acc2[rr][4] + bias, x1.x);
        r1.y = fmaf(gma, acc2[rr][5] + bias, x1.y);
        r1.z = fmaf(gma, acc2[rr][6] + bias, x1.z);
        r1.w = fmaf(gma, acc2[rr][7] + bias, x1.w);
        *(float4*)(out + off)     = r0;
        *(float4*)(out + off + 4) = r1;
    }
}

// =====================================================================
extern "C" void kernel_launch(void* const* d_in, const int* in_sizes, int n_in,
                              void* d_out, int out_size)
{
    (void)in_sizes; (void)n_in; (void)out_size;
    const float* x     = (const float*)d_in[0];
    const float* Wf    = (const float*)d_in[1];
    const float* bf    = (const float*)d_in[2];
    const float* Wg    = (const float*)d_in[3];
    const float* bg    = (const float*)d_in[4];
    const float* Wh    = (const float*)d_in[5];
    const float* bh    = (const float*)d_in[6];
    const float* Wo    = (const float*)d_in[7];
    const float* bo    = (const float*)d_in[8];
    const float* gamma = (const float*)d_in[9];
    float* out = (float*)d_out;

    // opt-in large dynamic smem (idempotent; safe under graph capture)
    cudaFuncSetAttribute(conv_pool_kernel,
                         cudaFuncAttributeMaxDynamicSharedMemorySize, 114688);
    cudaFuncSetAttribute(attn_out_kernel,
                         cudaFuncAttributeMaxDynamicSharedMemorySize, 66560);

    conv_pool_kernel<<<dim3(32, NB), 384, 114688>>>(x, Wf, bf, Wg, bg, Wh, bh);
    s_softmax_kernel<<<dim3(256, NB), 512>>>();
    attn_out_kernel<<<dim3(32, NB), 256, 66560>>>(x, Wo, bo, gamma, out);
}

// round 9
// speedup vs baseline: 1.0548x; 1.0021x over previous
#include <cuda_runtime.h>
#include <cstdint>
#include <cstddef>

// Problem constants
#define NB 16
#define NC 128
#define HW 4096          // 64*64
#define MP 1024          // pooled positions (32*32)
#define K8 16            // C/8
#define K2 64            // C/2

// ---------------- scratch (device globals; no allocation allowed) ----------------
__device__ __align__(16) float g_f[NB * K8 * MP];                 // 1 MB
__device__ __align__(16) float g_g[NB * K8 * HW];                 // 4 MB
__device__ __align__(16) float g_v[NB * K2 * MP];                 // 4 MB
__device__ __align__(16) float g_beta[(size_t)NB * MP * HW];      // 256 MB

// ---------------- helpers ----------------
__device__ __forceinline__ float wredmax(float v) {
#pragma unroll
    for (int o = 16; o > 0; o >>= 1) v = fmaxf(v, __shfl_xor_sync(0xffffffffu, v, o));
    return v;
}
__device__ __forceinline__ float wredsum(float v) {
#pragma unroll
    for (int o = 16; o > 0; o >>= 1) v += __shfl_xor_sync(0xffffffffu, v, o);
    return v;
}

// =====================================================================
// Kernel 1: fused 1x1 convs (f,g,h) + 2x2 maxpool for f,h.
// Grid: (32 row-pairs, 16 batches), 384 threads.
// Dynamic smem: xs[128][128] (64KB) + ws[96][128] (48KB, reused as cs[80][128])
// =====================================================================
__global__ void __launch_bounds__(384) conv_pool_kernel(
    const float* __restrict__ x,
    const float* __restrict__ Wf, const float* __restrict__ bf,
    const float* __restrict__ Wg, const float* __restrict__ bg,
    const float* __restrict__ Wh, const float* __restrict__ bh)
{
    extern __shared__ float sm1[];
    float* xs = sm1;            // [128][128]  pix-contiguous
    float* ws = sm1 + 16384;    // [96][128]   k rows: 0..15 f, 16..31 g, 32..95 h
    __shared__ float bs[96];

    const int tid = threadIdx.x;
    const int hp  = blockIdx.x;   // pooled row 0..31
    const int b   = blockIdx.y;

    // weights -> smem
    {
        const float4* wf4 = (const float4*)Wf;
        const float4* wg4 = (const float4*)Wg;
        const float4* wh4 = (const float4*)Wh;
        float4* ws4 = (float4*)ws;
        for (int i = tid; i < 512;  i += 384) ws4[i]        = wf4[i];
        for (int i = tid; i < 512;  i += 384) ws4[512 + i]  = wg4[i];
        for (int i = tid; i < 2048; i += 384) ws4[1024 + i] = wh4[i];
        if (tid < 96) bs[tid] = (tid < 16) ? bf[tid] : ((tid < 32) ? bg[tid - 16] : bh[tid - 32]);
    }
    // x slab: rows 2hp, 2hp+1 for all 128 channels; 128 contiguous floats per channel
    {
        float4* xs4 = (float4*)xs;
        for (int i = tid; i < 4096; i += 384) {
            int c = i >> 5, p4 = i & 31;
            xs4[i] = *((const float4*)(x + (size_t)(b * NC + c) * HW + hp * 128) + p4);
        }
    }
    __syncthreads();

    // each thread: 4 consecutive output channels (kq) x 8 pixels (pg)
    const int kq = tid >> 4;        // 0..23
    const int pg = tid & 15;        // 0..15
    const int k0 = kq * 4;
    const int px = pg * 8;

    float acc[4][8];
#pragma unroll
    for (int i = 0; i < 4; i++)
#pragma unroll
        for (int j = 0; j < 8; j++) acc[i][j] = 0.f;

    const float* wr0 = ws + (k0 + 0) * 128;
    const float* wr1 = ws + (k0 + 1) * 128;
    const float* wr2 = ws + (k0 + 2) * 128;
    const float* wr3 = ws + (k0 + 3) * 128;

#pragma unroll 2
    for (int c = 0; c < 128; c += 4) {
        float4 w0 = *(const float4*)(wr0 + c);
        float4 w1 = *(const float4*)(wr1 + c);
        float4 w2 = *(const float4*)(wr2 + c);
        float4 w3 = *(const float4*)(wr3 + c);
        float wa0[4] = {w0.x, w0.y, w0.z, w0.w};
        float wa1[4] = {w1.x, w1.y, w1.z, w1.w};
        float wa2[4] = {w2.x, w2.y, w2.z, w2.w};
        float wa3[4] = {w3.x, w3.y, w3.z, w3.w};
#pragma unroll
        for (int ci = 0; ci < 4; ci++) {
            float4 xa = *(const float4*)(xs + (c + ci) * 128 + px);
            float4 xb = *(const float4*)(xs + (c + ci) * 128 + px + 4);
            float xv[8] = {xa.x, xa.y, xa.z, xa.w, xb.x, xb.y, xb.z, xb.w};
#pragma unroll
            for (int j = 0; j < 8; j++) {
                acc[0][j] = fmaf(wa0[ci], xv[j], acc[0][j]);
                acc[1][j] = fmaf(wa1[ci], xv[j], acc[1][j]);
                acc[2][j] = fmaf(wa2[ci], xv[j], acc[2][j]);
                acc[3][j] = fmaf(wa3[ci], xv[j], acc[3][j]);
            }
        }
    }
    __syncthreads();   // done with xs & ws reads; ws region reused as cs below

    const int r    = pg >> 3;         // row within pair
    const int colb = (pg & 7) * 8;    // column base (0..56)

    if (kq >= 4 && kq < 8) {
        // g channels: full resolution, write directly
#pragma unroll
        for (int i = 0; i < 4; i++) {
            const int k = k0 + i;                 // 16..31
            const float bias = bs[k];
            float* gp = g_g + (size_t)(b * K8 + (k - 16)) * HW + (2 * hp + r) * 64 + colb;
            *(float4*)gp       = make_float4(acc[i][0] + bias, acc[i][1] + bias,
                                             acc[i][2] + bias, acc[i][3] + bias);
            *(float4*)(gp + 4) = make_float4(acc[i][4] + bias, acc[i][5] + bias,
                                             acc[i][6] + bias, acc[i][7] + bias);
        }
    } else {
        // f (k<16) and h (k>=32) channels: stage in smem for pooling
        float* cs = ws;   // [80][128]: 0..15 f, 16..79 h
#pragma unroll
        for (int i = 0; i < 4; i++) {
            const int k = k0 + i;
            const int kfh = (k < 16) ? k : (k - 16);
            const float bias = bs[k];
            float* dst = cs + kfh * 128 + px;
            *(float4*)dst       = make_float4(acc[i][0] + bias, acc[i][1] + bias,
                                              acc[i][2] + bias, acc[i][3] + bias);
            *(float4*)(dst + 4) = make_float4(acc[i][4] + bias, acc[i][5] + bias,
                                              acc[i][6] + bias, acc[i][7] + bias);
        }
    }
    __syncthreads();

    // 2x2 maxpool and writeout: 80 channels x 32 pooled cols
    for (int idx = tid; idx < 2560; idx += 384) {
        int k = idx >> 5, wc = idx & 31;
        const float* csr = ws + k * 128;
        float mv = fmaxf(fmaxf(csr[2 * wc], csr[2 * wc + 1]),
                         fmaxf(csr[64 + 2 * wc], csr[64 + 2 * wc + 1]));
        int m = hp * 32 + wc;
        if (k < 16) g_f[(size_t)(b * K8 + k) * MP + m]        = mv;
        else        g_v[(size_t)(b * K2 + (k - 16)) * MP + m] = mv;
    }
}

// =====================================================================
// Kernel 2: s = f^T g (K=16) fused with row softmax -> beta.  s never hits HBM.
// Grid: (256 m-groups of 4, 16 batches), 512 threads. Each thread: 4 rows x 8 cols.
// =====================================================================
__global__ void __launch_bounds__(512) s_softmax_kernel()
{
    const int b   = blockIdx.y;
    const int m0  = blockIdx.x * 4;
    const int tid = threadIdx.x;

    __shared__ float fs[16][4];
    __shared__ float red[4][16];

    if (tid < 64)
        fs[tid >> 2][tid & 3] = g_f[(size_t)(b * K8 + (tid >> 2)) * MP + m0 + (tid & 3)];
    __syncthreads();

    const float* gb = g_g + (size_t)b * K8 * HW;
    const int n0 = tid * 4;   // cols [n0,n0+3] and [2048+n0, 2048+n0+3]

    float acc[4][8];
#pragma unroll
    for (int mi = 0; mi < 4; mi++)
#pragma unroll
        for (int j = 0; j < 8; j++) acc[mi][j] = 0.f;

#pragma unroll
    for (int k = 0; k < 16; k++) {
        const float* gk = gb + (size_t)k * HW;
        float4 ga = *(const float4*)(gk + n0);
        float4 gc = *(const float4*)(gk + 2048 + n0);
        float gv[8] = {ga.x, ga.y, ga.z, ga.w, gc.x, gc.y, gc.z, gc.w};
#pragma unroll
        for (int mi = 0; mi < 4; mi++) {
            const float fv = fs[k][mi];
#pragma unroll
            for (int j = 0; j < 8; j++) acc[mi][j] = fmaf(fv, gv[j], acc[mi][j]);
        }
    }

    const int lane = tid & 31, wid = tid >> 5;

    // --- row max ---
    float rmx[4];
#pragma unroll
    for (int mi = 0; mi < 4; mi++) {
        float v = acc[mi][0];
#pragma unroll
        for (int j = 1; j < 8; j++) v = fmaxf(v, acc[mi][j]);
        rmx[mi] = wredmax(v);
    }
    if (lane == 0) {
#pragma unroll
        for (int mi = 0; mi < 4; mi++) red[mi][wid] = rmx[mi];
    }
    __syncthreads();
    float mxf[4];
#pragma unroll
    for (int mi = 0; mi < 4; mi++) {
        float v = red[mi][0];
#pragma unroll
        for (int w2 = 1; w2 < 16; w2++) v = fmaxf(v, red[mi][w2]);
        mxf[mi] = v;
    }
    __syncthreads();   // before reusing red[]

    // --- exp + row sum ---
    float sms[4];
#pragma unroll
    for (int mi = 0; mi < 4; mi++) {
        float s = 0.f;
#pragma unroll
        for (int j = 0; j < 8; j++) {
            acc[mi][j] = __expf(acc[mi][j] - mxf[mi]);
            s += acc[mi][j];
        }
        sms[mi] = wredsum(s);
    }
    if (lane == 0) {
#pragma unroll
        for (int mi = 0; mi < 4; mi++) red[mi][wid] = sms[mi];
    }
    __syncthreads();

#pragma unroll
    for (int mi = 0; mi < 4; mi++) {
        float s = 0.f;
#pragma unroll
        for (int w2 = 0; w2 < 16; w2++) s += red[mi][w2];
        const float inv = 1.0f / s;
        float* bp = g_beta + (size_t)(b * MP + m0 + mi) * HW + n0;
        *(float4*)bp          = make_float4(acc[mi][0] * inv, acc[mi][1] * inv,
                                            acc[mi][2] * inv, acc[mi][3] * inv);
        *(float4*)(bp + 2048) = make_float4(acc[mi][4] * inv, acc[mi][5] * inv,
                                            acc[mi][6] * inv, acc[mi][7] * inv);
    }
}

// =====================================================================
// Kernel 3: o = v @ beta  (64x4096 per batch, K=1024), fused with
// out = gamma*(Wo @ o + bo) + x.
// Grid: (32 column blocks of 128, 16 batches), 256 threads (tx 0..15, ty 0..15).
// Dyn smem: main loop As[32][68] + Bs[32][128]; epilogue Os[64][132] + WoT[64][128].
// =====================================================================
__global__ void __launch_bounds__(256) attn_out_kernel(
    const float* __restrict__ x, const float* __restrict__ Wo,
    const float* __restrict__ bo, const float* __restrict__ gammap,
    float* __restrict__ out)
{
    extern __shared__ float sm3[];
    float* As = sm3;           // [32][68]   (mi, k) with pad
    float* Bs = sm3 + 2176;    // [32][128]  (mi, n)

    const int b   = blockIdx.y;
    const int nb  = blockIdx.x * 128;
    const int tid = threadIdx.x;
    const int tx  = tid & 15, ty = tid >> 4;
    const int miL = tid & 31, kg = tid >> 5;

    const float* vB    = g_v    + (size_t)b * K2 * MP;
    const float* betaB = g_beta + (size_t)b * MP * HW + nb;

    float acc[4][8];
#pragma unroll
    for (int i = 0; i < 4; i++)
#pragma unroll
        for (int j = 0; j < 8; j++) acc[i][j] = 0.f;

    float  rA[8];
    float4 rB[4];

    // prefetch chunk 0
#pragma unroll
    for (int ii = 0; ii < 8; ii++) rA[ii] = vB[(size_t)(kg + ii * 8) * MP + miL];
#pragma unroll
    for (int it = 0; it < 4; it++) {
        int lin = it * 1024 + tid * 4;
        rB[it] = *(const float4*)(betaB + (size_t)(lin >> 7) * HW + (lin & 127));
    }
#pragma unroll
    for (int ii = 0; ii < 8; ii++) As[miL * 68 + kg + ii * 8] = rA[ii];
#pragma unroll
    for (int it = 0; it < 4; it++) *(float4*)(Bs + it * 1024 + tid * 4) = rB[it];
    __syncthreads();

    for (int c = 0; c < 32; c++) {
        const int mcn = (c + 1) * 32;
        if (c < 31) {
#pragma unroll
            for (int ii = 0; ii < 8; ii++)
                rA[ii] = vB[(size_t)(kg + ii * 8) * MP + mcn + miL];
#pragma unroll
            for (int it = 0; it < 4; it++) {
                int lin = it * 1024 + tid * 4;
                rB[it] = *(const float4*)(betaB + (size_t)(mcn + (lin >> 7)) * HW + (lin & 127));
            }
        }
#pragma unroll
        for (int mi = 0; mi < 32; mi++) {
            float4 a  = *(const float4*)(As + mi * 68 + ty * 4);
            float4 b0 = *(const float4*)(Bs + mi * 128 + tx * 8);
            float4 b1 = *(const float4*)(Bs + mi * 128 + tx * 8 + 4);
            float av[4] = {a.x, a.y, a.z, a.w};
            float bv[8] = {b0.x, b0.y, b0.z, b0.w, b1.x, b1.y, b1.z, b1.w};
#pragma unroll
            for (int i = 0; i < 4; i++)
#pragma unroll
                for (int j = 0; j < 8; j++)
                    acc[i][j] = fmaf(av[i], bv[j], acc[i][j]);
        }
        __syncthreads();
        if (c < 31) {
#pragma unroll
            for (int ii = 0; ii < 8; ii++) As[miL * 68 + kg + ii * 8] = rA[ii];
#pragma unroll
            for (int it = 0; it < 4; it++) *(float4*)(Bs + it * 1024 + tid * 4) = rB[it];
            __syncthreads();
        }
    }

    // ---------------- epilogue: out = gamma*(Wo @ o + bo) + x ----------------
    float* Os  = sm3;          // [64][132]
    float* WoT = sm3 + 8448;   // [64][128]  WoT[k][c] = Wo[c][k]

#pragma unroll
    for (int i2 = 0; i2 < 4; i2++) {
        int k = ty * 4 + i2;
        *(float4*)(Os + k * 132 + tx * 8)     = make_float4(acc[i2][0], acc[i2][1],
                                                            acc[i2][2], acc[i2][3]);
        *(float4*)(Os + k * 132 + tx * 8 + 4) = make_float4(acc[i2][4], acc[i2][5],
                                                            acc[i2][6], acc[i2][7]);
    }
    for (int i = tid; i < 8192; i += 256) {
        int k = i >> 7, cc = i & 127;
        WoT[i] = Wo[cc * 64 + k];
    }
    __syncthreads();

    const float gma = *gammap;
    float acc2[8][8];
#pragma unroll
    for (int i = 0; i < 8; i++)
#pragma unroll
        for (int j = 0; j < 8; j++) acc2[i][j] = 0.f;

#pragma unroll 4
    for (int k = 0; k < 64; k++) {
        float4 w0 = *(const float4*)(WoT + k * 128 + ty * 8);
        float4 w1 = *(const float4*)(WoT + k * 128 + ty * 8 + 4);
        float4 o0 = *(const float4*)(Os + k * 132 + tx * 8);
        float4 o1 = *(const float4*)(Os + k * 132 + tx * 8 + 4);
        float wv[8] = {w0.x, w0.y, w0.z, w0.w, w1.x, w1.y, w1.z, w1.w};
        float ov[8] = {o0.x, o0.y, o0.z, o0.w, o1.x, o1.y, o1.z, o1.w};
#pragma unroll
        for (int i = 0; i < 8; i++)
#pragma unroll
            for (int j = 0; j < 8; j++)
                acc2[i][j] = fmaf(wv[i], ov[j], acc2[i][j]);
    }

#pragma unroll
    for (int rr = 0; rr < 8; rr++) {
        const int cc = ty * 8 + rr;
        const float bias = bo[cc];
        const size_t off = (size_t)(b * NC + cc) * HW + nb + tx * 8;
        float4 x0 = *(const float4*)(x + off);
        float4 x1 = *(const float4*)(x + off + 4);
        float4 r0, r1;
        r0.x = fmaf(gma, acc2[rr][0] + bias, x0.x);
        r0.y = fmaf(gma, acc2[rr][1] + bias, x0.y);
        r0.z = fmaf(gma, acc2[rr][2] + bias, x0.z);
        r0.w = fmaf(gma, acc2[rr][3] + bias, x0.w);
        r1.x = fmaf(gma, acc2[rr][4] + bias, x1.x);
        r1.y = fmaf(gma, acc2[rr][5] + bias, x1.y);
        r1.z = fmaf(gma, acc2[rr][6] + bias, x1.z);
        r1.w = fmaf(gma, acc2[rr][7] + bias, x1.w);
        *(float4*)(out + off)     = r0;
        *(float4*)(out + off + 4) = r1;
    }
}

// =====================================================================
extern "C" void kernel_launch(void* const* d_in, const int* in_sizes, int n_in,
                              void* d_out, int out_size)
{
    (void)in_sizes; (void)n_in; (void)out_size;
    const float* x     = (const float*)d_in[0];
    const float* Wf    = (const float*)d_in[1];
    const float* bf    = (const float*)d_in[2];
    const float* Wg    = (const float*)d_in[3];
    const float* bg    = (const float*)d_in[4];
    const float* Wh    = (const float*)d_in[5];
    const float* bh    = (const float*)d_in[6];
    const float* Wo    = (const float*)d_in[7];
    const float* bo    = (const float*)d_in[8];
    const float* gamma = (const float*)d_in[9];
    float* out = (float*)d_out;

    // opt-in large dynamic smem (idempotent; safe under graph capture)
    cudaFuncSetAttribute(conv_pool_kernel,
                         cudaFuncAttributeMaxDynamicSharedMemorySize, 114688);
    cudaFuncSetAttribute(attn_out_kernel,
                         cudaFuncAttributeMaxDynamicSharedMemorySize, 66560);

    conv_pool_kernel<<<dim3(32, NB), 384, 114688>>>(x, Wf, bf, Wg, bg, Wh, bh);
    s_softmax_kernel<<<dim3(256, NB), 512>>>();
    attn_out_kernel<<<dim3(32, NB), 256, 66560>>>(x, Wo, bo, gamma, out);
}